// round 13
// baseline (speedup 1.0000x reference)
#include <cuda_runtime.h>
#include <cstdint>

#define ICC 128
#define OCC 128
#define BDIM 64
#define OD  1024
#define LL  2048
#define KC  8            // ic per chunk
#define DT  8            // d per block
#define OT  32           // o per block
#define XSTR 592         // bytes per (ic,dd) x-row: 64 float2 + 3 gaps + stagger
#define WSTR 272         // bytes per (ic,dd) w-row: 32 float2 + 1 gap
#define XS_B (64*XSTR)   // 37888
#define WS_B (64*WSTR)   // 17408
#define BUF_B (XS_B+WS_B)            // 55296
#define SMEM_B (2*BUF_B)             // 110592

using ull = unsigned long long;
#define FMA_F32X2(d_, a_, b_) \
  asm("fma.rn.f32x2 %0, %1, %2, %0;" : "+l"(d_) : "l"(a_), "l"(b_))

// padded column offsets: 16B gap after every 16 float2 (=128B)
static __device__ __forceinline__ int pcolx(int b) { return 8 * b + 16 * (b >> 4); }
static __device__ __forceinline__ int pcolw(int o) { return 8 * o + 16 * (o >> 4); }

__global__ void __launch_bounds__(512, 1)
nolc9(const float* __restrict__ X, const float* __restrict__ W,
      float* __restrict__ out)
{
    extern __shared__ __align__(16) char sm[];
    const int tid = threadIdx.x;
    const int oc0 = blockIdx.x * OT;
    const int d0  = blockIdx.y * DT;
    const int l0  = d0 * 2;
    const size_t RS = (size_t)ICC * LL;

    // compute map: warp = (dg, og); lane = (ty:8, tx:4)
    const int wid = tid >> 5, lane = tid & 31;
    const int dg = wid >> 1, og = wid & 1;
    const int ty = lane >> 2, tx = lane & 3;

    // loader map: lanes along l
    const int jj = tid & 3;
    const int rr = tid >> 2;

    float4 px[4], pw[2];
    ull acc[8][4];
    #pragma unroll
    for (int i = 0; i < 8; ++i)
        #pragma unroll
        for (int j = 0; j < 4; ++j) acc[i][j] = 0ull;

    auto LDG = [&](int c) {
        const int ic0 = c * KC;
        #pragma unroll
        for (int p = 0; p < 4; ++p) {
            int r = rr + 128 * p, b = r & 63, ic = r >> 6;
            px[p] = *reinterpret_cast<const float4*>(
                X + (size_t)b * RS + (size_t)(ic0 + ic) * LL + l0 + 4 * jj);
        }
        #pragma unroll
        for (int p = 0; p < 2; ++p) {
            int r = rr + 128 * p, o = r & 31, ic = r >> 5;
            pw[p] = *reinterpret_cast<const float4*>(
                W + (size_t)(oc0 + o) * RS + (size_t)(ic0 + ic) * LL + l0 + 4 * jj);
        }
    };
    auto STS = [&](int buf) {
        char* xs = sm + buf * BUF_B;
        char* ws = sm + buf * BUF_B + XS_B;
        #pragma unroll
        for (int p = 0; p < 4; ++p) {
            int r = rr + 128 * p, b = r & 63, ic = r >> 6;
            char* base = xs + pcolx(b);
            *reinterpret_cast<float2*>(base + (ic * DT + 2 * jj) * XSTR) =
                make_float2(px[p].x, px[p].y);
            *reinterpret_cast<float2*>(base + (ic * DT + 2 * jj + 1) * XSTR) =
                make_float2(px[p].z, px[p].w);
        }
        #pragma unroll
        for (int p = 0; p < 2; ++p) {
            int r = rr + 128 * p, o = r & 31, ic = r >> 5;
            char* base = ws + pcolw(o);
            *reinterpret_cast<float2*>(base + (ic * DT + 2 * jj) * WSTR) =
                make_float2(pw[p].x, pw[p].y);
            *reinterpret_cast<float2*>(base + (ic * DT + 2 * jj + 1) * WSTR) =
                make_float2(pw[p].z, pw[p].w);
        }
    };

    LDG(0);
    STS(0);
    __syncthreads();

    const int xoff = dg * XSTR + pcolx(8 * ty);        // within-chunk offsets
    const int woff = dg * WSTR + 144 * og + 32 * tx;   // pcolw(16*og+4*tx)

    int buf = 0;
    for (int c = 0; c < ICC / KC; ++c) {
        if (c + 1 < ICC / KC) LDG(c + 1);

        const char* xb = sm + buf * BUF_B + xoff;
        const char* wb = sm + buf * BUF_B + XS_B + woff;
        #pragma unroll
        for (int k = 0; k < KC; ++k) {
            const ulonglong2* xp = reinterpret_cast<const ulonglong2*>(
                xb + k * (DT * XSTR));
            const ulonglong2* wp = reinterpret_cast<const ulonglong2*>(
                wb + k * (DT * WSTR));
            ulonglong2 w01 = wp[0], w23 = wp[1];
            ull wv[4] = { w01.x, w01.y, w23.x, w23.y };
            ulonglong2 a0 = xp[0], a1 = xp[1], a2 = xp[2], a3 = xp[3];
            ull xv[8] = { a0.x, a0.y, a1.x, a1.y, a2.x, a2.y, a3.x, a3.y };
            #pragma unroll
            for (int bb = 0; bb < 8; ++bb)
                #pragma unroll
                for (int oo = 0; oo < 4; ++oo)
                    FMA_F32X2(acc[bb][oo], xv[bb], wv[oo]);
        }

        if (c + 1 < ICC / KC) STS(buf ^ 1);
        __syncthreads();
        buf ^= 1;
    }

    // ---- epilogue via smem transpose: 32B contiguous d-runs out ----
    const float scale = 0.08838834764831843f;  // 1/sqrt(128)
    float* eb = reinterpret_cast<float*>(sm);  // Ebuf[64][32][12]
    #pragma unroll
    for (int bb = 0; bb < 8; ++bb) {
        const int b = 8 * ty + bb;
        #pragma unroll
        for (int oo = 0; oo < 4; ++oo) {
            const int ol = 16 * og + 4 * tx + oo;
            float2 v = *reinterpret_cast<float2*>(&acc[bb][oo]);
            eb[(b * OT + ol) * 12 + dg] = (v.x + v.y) * scale;
        }
    }
    __syncthreads();
    #pragma unroll
    for (int i = 0; i < 8; ++i) {
        int s = i * 512 + tid;
        int j = s & 1, row = s >> 1;           // row = b*32 + o
        int b = row >> 5, o = row & 31;
        float4 v = *reinterpret_cast<const float4*>(eb + row * 12 + 4 * j);
        *reinterpret_cast<float4*>(
            out + ((size_t)b * OCC + oc0 + o) * OD + d0 + 4 * j) = v;
    }
}

extern "C" void kernel_launch(void* const* d_in, const int* in_sizes, int n_in,
                              void* d_out, int out_size)
{
    const void* xa = d_in[0];
    const void* wa = d_in[1];
    if (n_in >= 2 && in_sizes[0] == OCC * ICC * LL &&
        in_sizes[1] == BDIM * ICC * LL) {
        const void* t = xa; xa = wa; wa = t;   // defensive: order swapped
    }
    cudaFuncSetAttribute(nolc9, cudaFuncAttributeMaxDynamicSharedMemorySize,
                         SMEM_B);
    dim3 grid(OCC / OT, OD / DT);              // (4, 128), oc fastest
    nolc9<<<grid, 512, SMEM_B>>>(reinterpret_cast<const float*>(xa),
                                 reinterpret_cast<const float*>(wa),
                                 reinterpret_cast<float*>(d_out));
}